// round 1
// baseline (speedup 1.0000x reference)
#include <cuda_runtime.h>
#include <cstddef>

// Problem: B=64, T=512, F=1024
//   mean/var over all of x; y = (x-mean)*rsqrt(var+eps)*gamma + beta
//   out[b,t,f] = x[b,t,f] + relu( sum_{t'} y[b,t',f] * W[t,t'] + bias[t] )
// GEMM view per batch b: A[f,t'] = y[b,t',f] (M=F), B[t',u] = W[u,t'] (N=T), K=T.

#define BSZ  64
#define TDIM 512
#define FDIM 1024
#define NTOT (BSZ * TDIM * FDIM)   // 33554432
#define EPSV 1e-5f

#define RED_BLOCKS  2048
#define RED_THREADS 256

// Scratch (no allocations allowed) — device globals.
__device__ float g_partial[2 * RED_BLOCKS];
__device__ float g_stats[2];   // {scale, shift}:  y = x*scale + shift

// ---------------------------------------------------------------------------
// Kernel 1: per-block partial sum & sum-of-squares over x (float4 loads).
// ---------------------------------------------------------------------------
__global__ void reduce_partials(const float* __restrict__ x) {
    const int tid = threadIdx.x;
    const float4* __restrict__ x4 = (const float4*)x;
    const long total4 = NTOT / 4;
    const long stride = (long)RED_BLOCKS * RED_THREADS;

    float s = 0.f, ss = 0.f;
    for (long i = (long)blockIdx.x * RED_THREADS + tid; i < total4; i += stride) {
        float4 v = x4[i];
        s  += (v.x + v.y) + (v.z + v.w);
        ss += (v.x * v.x + v.y * v.y) + (v.z * v.z + v.w * v.w);
    }

    __shared__ float sh0[RED_THREADS];
    __shared__ float sh1[RED_THREADS];
    sh0[tid] = s; sh1[tid] = ss;
    __syncthreads();
#pragma unroll
    for (int o = RED_THREADS / 2; o > 0; o >>= 1) {
        if (tid < o) { sh0[tid] += sh0[tid + o]; sh1[tid] += sh1[tid + o]; }
        __syncthreads();
    }
    if (tid == 0) {
        g_partial[blockIdx.x]              = sh0[0];
        g_partial[RED_BLOCKS + blockIdx.x] = sh1[0];
    }
}

// ---------------------------------------------------------------------------
// Kernel 2: final reduce of partials -> scale/shift.
// ---------------------------------------------------------------------------
__global__ void finalize_stats(const float* __restrict__ gamma,
                               const float* __restrict__ beta) {
    const int tid = threadIdx.x;   // 1024 threads
    float s  = g_partial[tid]              + g_partial[tid + 1024];
    float ss = g_partial[RED_BLOCKS + tid] + g_partial[RED_BLOCKS + tid + 1024];

    __shared__ float sh0[1024];
    __shared__ float sh1[1024];
    sh0[tid] = s; sh1[tid] = ss;
    __syncthreads();
#pragma unroll
    for (int o = 512; o > 0; o >>= 1) {
        if (tid < o) { sh0[tid] += sh0[tid + o]; sh1[tid] += sh1[tid + o]; }
        __syncthreads();
    }
    if (tid == 0) {
        const float invN = 1.0f / (float)NTOT;
        float mean = sh0[0] * invN;
        float var  = sh1[0] * invN - mean * mean;
        float scale = gamma[0] * rsqrtf(var + EPSV);
        g_stats[0] = scale;
        g_stats[1] = beta[0] - mean * scale;
    }
}

// ---------------------------------------------------------------------------
// Kernel 3: fused normalized-GEMM + bias + ReLU + residual.
// Tile: 128(f) x 128(u), BK=8, 256 threads, 8x8 microtile, double-buffered.
// ---------------------------------------------------------------------------
#define BM 128
#define BN 128
#define BK 8
#define KITERS (TDIM / BK)   // 64

__global__ __launch_bounds__(256, 2)
void gemm_fused(const float* __restrict__ x, const float* __restrict__ W,
                const float* __restrict__ bias, float* __restrict__ out) {
    __shared__ float As[2][BK][BM];        // As[k][f] = y(b, k0+k, f0+f)
    __shared__ float Ws[2][BK][BN + 4];    // Ws[k][u] = W(u0+u, k0+k); pad -> conflict-free

    const float scale = g_stats[0];
    const float shift = g_stats[1];

    const int b  = blockIdx.z;
    const int f0 = blockIdx.x * BM;
    const int u0 = blockIdx.y * BN;
    const int tid = threadIdx.x;
    const int tx = tid & 15;      // f group
    const int ty = tid >> 4;      // u group

    const float* __restrict__ xb = x + (size_t)b * TDIM * FDIM;

    // Loader mapping
    const int ak = tid >> 5;            // 0..7  (k row of A tile)
    const int af = (tid & 31) * 4;      // 0..124
    const int wu = tid >> 1;            // 0..127 (u row of W tile)
    const int wk = (tid & 1) * 4;       // 0 or 4

    const float* __restrict__ aptr = xb + (size_t)ak * FDIM + f0 + af;
    const float* __restrict__ wptr = W + (size_t)(u0 + wu) * TDIM + wk;

    // Prologue: load tile 0
    {
        float4 a = *(const float4*)aptr;
        float4 w = *(const float4*)wptr;
        a.x = a.x * scale + shift; a.y = a.y * scale + shift;
        a.z = a.z * scale + shift; a.w = a.w * scale + shift;
        *(float4*)&As[0][ak][af] = a;
        Ws[0][wk + 0][wu] = w.x; Ws[0][wk + 1][wu] = w.y;
        Ws[0][wk + 2][wu] = w.z; Ws[0][wk + 3][wu] = w.w;
    }
    __syncthreads();

    float acc[8][8];
#pragma unroll
    for (int i = 0; i < 8; i++)
#pragma unroll
        for (int j = 0; j < 8; j++) acc[i][j] = 0.f;

    int buf = 0;
    for (int it = 1; it <= KITERS; ++it) {
        const bool more = (it < KITERS);
        float4 aN, wN;
        if (more) {
            aN = *(const float4*)(aptr + (size_t)it * BK * FDIM);
            wN = *(const float4*)(wptr + it * BK);
        }

#pragma unroll
        for (int k = 0; k < BK; k++) {
            float a[8], w[8];
            *(float4*)(a)     = *(const float4*)&As[buf][k][tx * 4];
            *(float4*)(a + 4) = *(const float4*)&As[buf][k][tx * 4 + 64];
            *(float4*)(w)     = *(const float4*)&Ws[buf][k][ty * 4];
            *(float4*)(w + 4) = *(const float4*)&Ws[buf][k][ty * 4 + 64];
#pragma unroll
            for (int i = 0; i < 8; i++)
#pragma unroll
                for (int j = 0; j < 8; j++)
                    acc[i][j] = fmaf(w[i], a[j], acc[i][j]);
        }

        if (more) {
            aN.x = aN.x * scale + shift; aN.y = aN.y * scale + shift;
            aN.z = aN.z * scale + shift; aN.w = aN.w * scale + shift;
            *(float4*)&As[buf ^ 1][ak][af] = aN;
            Ws[buf ^ 1][wk + 0][wu] = wN.x; Ws[buf ^ 1][wk + 1][wu] = wN.y;
            Ws[buf ^ 1][wk + 2][wu] = wN.z; Ws[buf ^ 1][wk + 3][wu] = wN.w;
            __syncthreads();
            buf ^= 1;
        }
    }

    // Epilogue: out[b, u, f] = x[b, u, f] + relu(acc + bias[u])
#pragma unroll
    for (int ii = 0; ii < 8; ii++) {
        const int u = u0 + ((ii < 4) ? (ty * 4 + ii) : (64 + ty * 4 + (ii - 4)));
        const float bv = __ldg(&bias[u]);
        const size_t row = ((size_t)b * TDIM + u) * FDIM + f0;

        float4 x0 = *(const float4*)(x + row + tx * 4);
        float4 x1 = *(const float4*)(x + row + 64 + tx * 4);
        float4 o0, o1;
        o0.x = x0.x + fmaxf(acc[ii][0] + bv, 0.f);
        o0.y = x0.y + fmaxf(acc[ii][1] + bv, 0.f);
        o0.z = x0.z + fmaxf(acc[ii][2] + bv, 0.f);
        o0.w = x0.w + fmaxf(acc[ii][3] + bv, 0.f);
        o1.x = x1.x + fmaxf(acc[ii][4] + bv, 0.f);
        o1.y = x1.y + fmaxf(acc[ii][5] + bv, 0.f);
        o1.z = x1.z + fmaxf(acc[ii][6] + bv, 0.f);
        o1.w = x1.w + fmaxf(acc[ii][7] + bv, 0.f);
        *(float4*)(out + row + tx * 4)      = o0;
        *(float4*)(out + row + 64 + tx * 4) = o1;
    }
}

// ---------------------------------------------------------------------------
extern "C" void kernel_launch(void* const* d_in, const int* in_sizes, int n_in,
                              void* d_out, int out_size) {
    const float* x     = (const float*)d_in[0];
    const float* W     = (const float*)d_in[1];
    const float* bias  = (const float*)d_in[2];
    const float* gamma = (const float*)d_in[3];
    const float* beta  = (const float*)d_in[4];
    float* out = (float*)d_out;

    reduce_partials<<<RED_BLOCKS, RED_THREADS>>>(x);
    finalize_stats<<<1, 1024>>>(gamma, beta);

    dim3 grid(FDIM / BM, TDIM / BN, BSZ);
    gemm_fused<<<grid, 256>>>(x, W, bias, out);
}

// round 3
// speedup vs baseline: 1.9544x; 1.9544x over previous
#include <cuda_runtime.h>
#include <cuda_bf16.h>
#include <cstdint>
#include <cstddef>

// Problem: B=64, T=512, F=1024
//   stats over all x; y = x*scale + shift
//   out[b,t,f] = x[b,t,f] + relu( sum_t' y[b,t',f] * W[t,t'] + bias[t] )
// GEMM per b: D[f,u] = sum_k A[f,k]*Bm[u,k], A[f,k]=y[b,k,f], Bm[u,k]=W[u,k]
// bf16 hi/lo split: D = Ah*Bh + Ah*Bl + Al*Bh (fp32 accum), via mma.sync HMMA.

#define BSZ  64
#define TDIM 512
#define FDIM 1024
#define NTOT (BSZ * TDIM * FDIM)
#define EPSV 1e-5f

#define RED_BLOCKS  2048
#define RED_THREADS 256

__device__ float g_partial[2 * RED_BLOCKS];
__device__ float g_stats[2];   // {scale, shift}

__device__ __nv_bfloat16 g_yT_hi[(size_t)BSZ * FDIM * TDIM];  // [b][f][t]
__device__ __nv_bfloat16 g_yT_lo[(size_t)BSZ * FDIM * TDIM];
__device__ __nv_bfloat16 g_w_hi[TDIM * TDIM];                 // [u][t]
__device__ __nv_bfloat16 g_w_lo[TDIM * TDIM];

// ---------------------------------------------------------------------------
__device__ __forceinline__ uint32_t smem_u32(const void* p) {
    uint32_t a;
    asm("{ .reg .u64 t; cvta.to.shared.u64 t, %1; cvt.u32.u64 %0, t; }"
        : "=r"(a) : "l"(p));
    return a;
}
__device__ __forceinline__ void cp16(uint32_t s, const void* g) {
    asm volatile("cp.async.cg.shared.global [%0], [%1], 16;" :: "r"(s), "l"(g) : "memory");
}
__device__ __forceinline__ void ldsm4(uint32_t& r0, uint32_t& r1, uint32_t& r2,
                                      uint32_t& r3, uint32_t addr) {
    asm volatile("ldmatrix.sync.aligned.m8n8.x4.shared.b16 {%0,%1,%2,%3}, [%4];"
                 : "=r"(r0), "=r"(r1), "=r"(r2), "=r"(r3) : "r"(addr));
}
__device__ __forceinline__ void mma16816(float* c, const uint32_t* a, const uint32_t* b) {
    asm volatile("mma.sync.aligned.m16n8k16.row.col.f32.bf16.bf16.f32 "
                 "{%0,%1,%2,%3}, {%4,%5,%6,%7}, {%8,%9}, {%0,%1,%2,%3};"
                 : "+f"(c[0]), "+f"(c[1]), "+f"(c[2]), "+f"(c[3])
                 : "r"(a[0]), "r"(a[1]), "r"(a[2]), "r"(a[3]), "r"(b[0]), "r"(b[1]));
}

// ---------------------------------------------------------------------------
// Kernel 1: partial sum / sumsq
// ---------------------------------------------------------------------------
__global__ void reduce_partials(const float* __restrict__ x) {
    const int tid = threadIdx.x;
    const float4* __restrict__ x4 = (const float4*)x;
    const long total4 = NTOT / 4;
    const long stride = (long)RED_BLOCKS * RED_THREADS;
    float s = 0.f, ss = 0.f;
    for (long i = (long)blockIdx.x * RED_THREADS + tid; i < total4; i += stride) {
        float4 v = x4[i];
        s  += (v.x + v.y) + (v.z + v.w);
        ss += (v.x * v.x + v.y * v.y) + (v.z * v.z + v.w * v.w);
    }
    __shared__ float sh0[RED_THREADS], sh1[RED_THREADS];
    sh0[tid] = s; sh1[tid] = ss;
    __syncthreads();
#pragma unroll
    for (int o = RED_THREADS / 2; o > 0; o >>= 1) {
        if (tid < o) { sh0[tid] += sh0[tid + o]; sh1[tid] += sh1[tid + o]; }
        __syncthreads();
    }
    if (tid == 0) {
        g_partial[blockIdx.x]              = sh0[0];
        g_partial[RED_BLOCKS + blockIdx.x] = sh1[0];
    }
}

// ---------------------------------------------------------------------------
// Kernel 2: finalize stats
// ---------------------------------------------------------------------------
__global__ void finalize_stats(const float* __restrict__ gamma,
                               const float* __restrict__ beta) {
    const int tid = threadIdx.x;   // 1024
    float s  = g_partial[tid]              + g_partial[tid + 1024];
    float ss = g_partial[RED_BLOCKS + tid] + g_partial[RED_BLOCKS + tid + 1024];
    __shared__ float sh0[1024], sh1[1024];
    sh0[tid] = s; sh1[tid] = ss;
    __syncthreads();
#pragma unroll
    for (int o = 512; o > 0; o >>= 1) {
        if (tid < o) { sh0[tid] += sh0[tid + o]; sh1[tid] += sh1[tid + o]; }
        __syncthreads();
    }
    if (tid == 0) {
        const float invN = 1.0f / (float)NTOT;
        float mean = sh0[0] * invN;
        float var  = sh1[0] * invN - mean * mean;
        float scale = gamma[0] * rsqrtf(var + EPSV);
        g_stats[0] = scale;
        g_stats[1] = beta[0] - mean * scale;
    }
}

// ---------------------------------------------------------------------------
// Kernel 3: W -> bf16 hi/lo
// ---------------------------------------------------------------------------
__global__ void split_w(const float* __restrict__ W) {
    int i = blockIdx.x * 256 + threadIdx.x;
    float w = W[i];
    __nv_bfloat16 h = __float2bfloat16(w);
    g_w_hi[i] = h;
    g_w_lo[i] = __float2bfloat16(w - __bfloat162float(h));
}

// ---------------------------------------------------------------------------
// Kernel 4: normalize + transpose + split: x[b,t,f] -> yT_{hi,lo}[b,f,t]
// ---------------------------------------------------------------------------
__global__ void convert_transpose(const float* __restrict__ x) {
    __shared__ float tile[32][33];
    const int b = blockIdx.z, t0 = blockIdx.x * 32, f0 = blockIdx.y * 32;
    const int tx = threadIdx.x, ty = threadIdx.y;   // 32 x 8
    const float scale = g_stats[0], shift = g_stats[1];
    const float* __restrict__ xb = x + ((size_t)b * TDIM + t0) * FDIM + f0;
#pragma unroll
    for (int j = 0; j < 32; j += 8)
        tile[ty + j][tx] = xb[(size_t)(ty + j) * FDIM + tx];
    __syncthreads();
    __nv_bfloat16* __restrict__ ph = g_yT_hi + ((size_t)b * FDIM + f0) * TDIM + t0;
    __nv_bfloat16* __restrict__ pl = g_yT_lo + ((size_t)b * FDIM + f0) * TDIM + t0;
#pragma unroll
    for (int j = 0; j < 32; j += 8) {
        float y = fmaf(tile[tx][ty + j], scale, shift);
        __nv_bfloat16 h = __float2bfloat16(y);
        float r = y - __bfloat162float(h);
        ph[(size_t)(ty + j) * TDIM + tx] = h;
        pl[(size_t)(ty + j) * TDIM + tx] = __float2bfloat16(r);
    }
}

// ---------------------------------------------------------------------------
// Kernel 5: bf16 mma.sync GEMM + fused epilogue
// CTA tile 128(f) x 128(u), BK=32, 256 threads = 8 warps in 2(m) x 4(n),
// warp tile 64 x 32 via m16n8k16; double-buffered cp.async stages.
// ---------------------------------------------------------------------------
#define GM 128
#define GN 128
#define GBK 32
#define NSTAGE 16           // K / GBK
#define ROWB 80             // bytes per smem row (32 bf16 + 8 pad)

// per stage: Ah, Al, Bh, Bl each 128 rows x 80B = 10240B
#define PL_SZ   10240
#define STAGE_SZ (4 * PL_SZ)        // 40960
#define SMEM_SZ  (2 * STAGE_SZ)     // 81920 (epilogue reuses: 128*132*4=67584)

__global__ __launch_bounds__(256, 2)
void gemm_tc(const float* __restrict__ x, const float* __restrict__ bias,
             float* __restrict__ out) {
    extern __shared__ char smem[];
    const uint32_t sb = smem_u32(smem);
    const int tid = threadIdx.x, wid = tid >> 5, lid = tid & 31;
    const int wm = wid >> 2, wn = wid & 3;           // 2 x 4 warp grid
    const int b = blockIdx.z, f0 = blockIdx.x * GM, u0 = blockIdx.y * GN;

    const __nv_bfloat16* __restrict__ Ah = g_yT_hi + ((size_t)b * FDIM + f0) * TDIM;
    const __nv_bfloat16* __restrict__ Al = g_yT_lo + ((size_t)b * FDIM + f0) * TDIM;
    const __nv_bfloat16* __restrict__ Bh = g_w_hi + (size_t)u0 * TDIM;
    const __nv_bfloat16* __restrict__ Bl = g_w_lo + (size_t)u0 * TDIM;

    // loader mapping: idx in [0,512): row=idx/4, chunk c=idx%4 (16B each)
    const int r0i = tid >> 2, c0i = tid & 3;               // idx = tid
    const int r1i = (tid + 256) >> 2, c1i = tid & 3;       // idx = tid + 256
    const uint32_t so0 = (uint32_t)(r0i * ROWB + c0i * 16);
    const uint32_t so1 = (uint32_t)(r1i * ROWB + c1i * 16);

    // ldmatrix lane offsets
    const uint32_t a_off = (uint32_t)((wm * 64 + (lid & 15)) * ROWB + (lid >> 4) * 16);
    const uint32_t b_off = (uint32_t)((wn * 32 + (lid & 7) + (lid >> 4) * 8) * ROWB
                                      + ((lid >> 3) & 1) * 16);

    float acc[4][4][4];
#pragma unroll
    for (int i = 0; i < 4; i++)
#pragma unroll
        for (int j = 0; j < 4; j++)
#pragma unroll
            for (int q = 0; q < 4; q++) acc[i][j][q] = 0.f;

    // ---- prologue: issue stages 0 and 1
#pragma unroll
    for (int s = 0; s < 2; s++) {
        const uint32_t st = sb + s * STAGE_SZ;
        const int k0 = s * GBK;
        const size_t g0 = (size_t)r0i * TDIM + k0 + c0i * 8;
        const size_t g1 = (size_t)r1i * TDIM + k0 + c1i * 8;
        cp16(st + so0,              Ah + g0);  cp16(st + so1,              Ah + g1);
        cp16(st + PL_SZ + so0,      Al + g0);  cp16(st + PL_SZ + so1,      Al + g1);
        cp16(st + 2 * PL_SZ + so0,  Bh + g0);  cp16(st + 2 * PL_SZ + so1,  Bh + g1);
        cp16(st + 3 * PL_SZ + so0,  Bl + g0);  cp16(st + 3 * PL_SZ + so1,  Bl + g1);
        asm volatile("cp.async.commit_group;" ::: "memory");
    }

    for (int kc = 0; kc < NSTAGE; kc++) {
        if (kc < NSTAGE - 1)
            asm volatile("cp.async.wait_group 1;" ::: "memory");
        else
            asm volatile("cp.async.wait_group 0;" ::: "memory");
        __syncthreads();

        const uint32_t st = sb + (kc & 1) * STAGE_SZ;
#pragma unroll
        for (int ks = 0; ks < 2; ks++) {
            const uint32_t kb = ks * 32;   // 16 elems * 2B
            uint32_t ah[4][4], al[4][4], bh[2][4], bl[2][4];
#pragma unroll
            for (int mt = 0; mt < 4; mt++)
                ldsm4(ah[mt][0], ah[mt][1], ah[mt][2], ah[mt][3],
                      st + a_off + mt * (16 * ROWB) + kb);
#pragma unroll
            for (int nt = 0; nt < 2; nt++)
                ldsm4(bh[nt][0], bh[nt][1], bh[nt][2], bh[nt][3],
                      st + 2 * PL_SZ + b_off + nt * (16 * ROWB) + kb);
            // Ah * Bh
#pragma unroll
            for (int mt = 0; mt < 4; mt++)
#pragma unroll
                for (int nf = 0; nf < 4; nf++)
                    mma16816(acc[mt][nf], ah[mt], &bh[nf >> 1][(nf & 1) * 2]);
            // Ah * Bl
#pragma unroll
            for (int nt = 0; nt < 2; nt++)
                ldsm4(bl[nt][0], bl[nt][1], bl[nt][2], bl[nt][3],
                      st + 3 * PL_SZ + b_off + nt * (16 * ROWB) + kb);
#pragma unroll
            for (int mt = 0; mt < 4; mt++)
#pragma unroll
                for (int nf = 0; nf < 4; nf++)
                    mma16816(acc[mt][nf], ah[mt], &bl[nf >> 1][(nf & 1) * 2]);
            // Al * Bh
#pragma unroll
            for (int mt = 0; mt < 4; mt++)
                ldsm4(al[mt][0], al[mt][1], al[mt][2], al[mt][3],
                      st + PL_SZ + a_off + mt * (16 * ROWB) + kb);
#pragma unroll
            for (int mt = 0; mt < 4; mt++)
#pragma unroll
                for (int nf = 0; nf < 4; nf++)
                    mma16816(acc[mt][nf], al[mt], &bh[nf >> 1][(nf & 1) * 2]);
        }
        __syncthreads();

        if (kc + 2 < NSTAGE) {
            const uint32_t st2 = sb + (kc & 1) * STAGE_SZ;   // buffer being refilled
            const int k0 = (kc + 2) * GBK;
            const size_t g0 = (size_t)r0i * TDIM + k0 + c0i * 8;
            const size_t g1 = (size_t)r1i * TDIM + k0 + c1i * 8;
            cp16(st2 + so0,             Ah + g0);  cp16(st2 + so1,             Ah + g1);
            cp16(st2 + PL_SZ + so0,     Al + g0);  cp16(st2 + PL_SZ + so1,     Al + g1);
            cp16(st2 + 2 * PL_SZ + so0, Bh + g0);  cp16(st2 + 2 * PL_SZ + so1, Bh + g1);
            cp16(st2 + 3 * PL_SZ + so0, Bl + g0);  cp16(st2 + 3 * PL_SZ + so1, Bl + g1);
            asm volatile("cp.async.commit_group;" ::: "memory");
        }
    }

    // ---- epilogue: transpose through smem, then coalesced f-major stores
    float* __restrict__ S = (float*)smem;     // [u_local][f_local], stride 132
    const int qrow = lid >> 2, qcol = (lid & 3) * 2;
#pragma unroll
    for (int mt = 0; mt < 4; mt++)
#pragma unroll
        for (int nf = 0; nf < 4; nf++) {
            const int fl = wm * 64 + mt * 16 + qrow;
            const int ul = wn * 32 + nf * 8 + qcol;
            S[(ul)     * 132 + fl]     = acc[mt][nf][0];
            S[(ul + 1) * 132 + fl]     = acc[mt][nf][1];
            S[(ul)     * 132 + fl + 8] = acc[mt][nf][2];
            S[(ul + 1) * 132 + fl + 8] = acc[mt][nf][3];
        }
    __syncthreads();

    const int fl4 = (tid & 31) * 4, ur = tid >> 5;   // 8 u rows per pass
#pragma unroll
    for (int up = 0; up < 16; up++) {
        const int ul = up * 8 + ur;
        const int u = u0 + ul;
        const float bv = __ldg(&bias[u]);
        const size_t gidx = ((size_t)b * TDIM + u) * FDIM + f0 + fl4;
        float4 xv = *(const float4*)(x + gidx);
        const float* sp = S + ul * 132 + fl4;
        float4 o;
        o.x = xv.x + fmaxf(sp[0] + bv, 0.f);
        o.y = xv.y + fmaxf(sp[1] + bv, 0.f);
        o.z = xv.z + fmaxf(sp[2] + bv, 0.f);
        o.w = xv.w + fmaxf(sp[3] + bv, 0.f);
        *(float4*)(out + gidx) = o;
    }
}

// ---------------------------------------------------------------------------
extern "C" void kernel_launch(void* const* d_in, const int* in_sizes, int n_in,
                              void* d_out, int out_size) {
    const float* x     = (const float*)d_in[0];
    const float* W     = (const float*)d_in[1];
    const float* bias  = (const float*)d_in[2];
    const float* gamma = (const float*)d_in[3];
    const float* beta  = (const float*)d_in[4];
    float* out = (float*)d_out;

    static bool attr_set = false;
    if (!attr_set) {
        cudaFuncSetAttribute(gemm_tc, cudaFuncAttributeMaxDynamicSharedMemorySize, SMEM_SZ);
        attr_set = true;
    }

    reduce_partials<<<RED_BLOCKS, RED_THREADS>>>(x);
    finalize_stats<<<1, 1024>>>(gamma, beta);
    split_w<<<(TDIM * TDIM) / 256, 256>>>(W);
    convert_transpose<<<dim3(TDIM / 32, FDIM / 32, BSZ), dim3(32, 8)>>>(x);

    dim3 grid(FDIM / GM, TDIM / GN, BSZ);
    gemm_tc<<<grid, 256, SMEM_SZ>>>(x, bias, out);
}

// round 4
// speedup vs baseline: 2.7095x; 1.3863x over previous
#include <cuda_runtime.h>
#include <cuda_fp16.h>
#include <cstdint>
#include <cstddef>

// Problem: B=64, T=512, F=1024
//   stats over all x; y = x*scale + shift
//   out[b,t,f] = x[b,t,f] + relu( sum_t' y[b,t',f] * W[t,t'] + bias[t] )
// GEMM per b: D[f,u] = sum_k A[f,k]*Bm[u,k], A[f,k]=y[b,k,f], Bm[u,k]=W[u,k]
// fp16 2-term: D = Ah*Wh + Ah*Wl  (Wh+Wl = W to 2^-22; error = (A-Ah)*W ~ 1e-4)

#define BSZ  64
#define TDIM 512
#define FDIM 1024
#define NTOT (BSZ * TDIM * FDIM)
#define EPSV 1e-5f

#define RED_BLOCKS  2048
#define RED_THREADS 256

__device__ float g_partial[2 * RED_BLOCKS];
__device__ float g_stats[2];   // {scale, shift}

__device__ __align__(16) __half g_yT_h[(size_t)BSZ * FDIM * TDIM];  // [b][f][t]
__device__ __align__(16) __half g_w_h[TDIM * TDIM];                 // [u][t]
__device__ __align__(16) __half g_w_l[TDIM * TDIM];

// ---------------------------------------------------------------------------
__device__ __forceinline__ uint32_t smem_u32(const void* p) {
    uint32_t a;
    asm("{ .reg .u64 t; cvta.to.shared.u64 t, %1; cvt.u32.u64 %0, t; }"
        : "=r"(a) : "l"(p));
    return a;
}
__device__ __forceinline__ void cp16(uint32_t s, const void* g) {
    asm volatile("cp.async.cg.shared.global [%0], [%1], 16;" :: "r"(s), "l"(g) : "memory");
}
__device__ __forceinline__ void ldsm4(uint32_t* r, uint32_t addr) {
    asm volatile("ldmatrix.sync.aligned.m8n8.x4.shared.b16 {%0,%1,%2,%3}, [%4];"
                 : "=r"(r[0]), "=r"(r[1]), "=r"(r[2]), "=r"(r[3]) : "r"(addr));
}
__device__ __forceinline__ void mma16816(float* c, const uint32_t* a, const uint32_t* b) {
    asm volatile("mma.sync.aligned.m16n8k16.row.col.f32.f16.f16.f32 "
                 "{%0,%1,%2,%3}, {%4,%5,%6,%7}, {%8,%9}, {%0,%1,%2,%3};"
                 : "+f"(c[0]), "+f"(c[1]), "+f"(c[2]), "+f"(c[3])
                 : "r"(a[0]), "r"(a[1]), "r"(a[2]), "r"(a[3]), "r"(b[0]), "r"(b[1]));
}

// ---------------------------------------------------------------------------
// Kernel 1: partial sum / sumsq
// ---------------------------------------------------------------------------
__global__ void reduce_partials(const float* __restrict__ x) {
    const int tid = threadIdx.x;
    const float4* __restrict__ x4 = (const float4*)x;
    const long total4 = NTOT / 4;
    const long stride = (long)RED_BLOCKS * RED_THREADS;
    float s = 0.f, ss = 0.f;
    for (long i = (long)blockIdx.x * RED_THREADS + tid; i < total4; i += stride) {
        float4 v = x4[i];
        s  += (v.x + v.y) + (v.z + v.w);
        ss += (v.x * v.x + v.y * v.y) + (v.z * v.z + v.w * v.w);
    }
    __shared__ float sh0[RED_THREADS], sh1[RED_THREADS];
    sh0[tid] = s; sh1[tid] = ss;
    __syncthreads();
#pragma unroll
    for (int o = RED_THREADS / 2; o > 0; o >>= 1) {
        if (tid < o) { sh0[tid] += sh0[tid + o]; sh1[tid] += sh1[tid + o]; }
        __syncthreads();
    }
    if (tid == 0) {
        g_partial[blockIdx.x]              = sh0[0];
        g_partial[RED_BLOCKS + blockIdx.x] = sh1[0];
    }
}

// ---------------------------------------------------------------------------
// Kernel 2: finalize stats
// ---------------------------------------------------------------------------
__global__ void finalize_stats(const float* __restrict__ gamma,
                               const float* __restrict__ beta) {
    const int tid = threadIdx.x;   // 1024
    float s  = g_partial[tid]              + g_partial[tid + 1024];
    float ss = g_partial[RED_BLOCKS + tid] + g_partial[RED_BLOCKS + tid + 1024];
    __shared__ float sh0[1024], sh1[1024];
    sh0[tid] = s; sh1[tid] = ss;
    __syncthreads();
#pragma unroll
    for (int o = 512; o > 0; o >>= 1) {
        if (tid < o) { sh0[tid] += sh0[tid + o]; sh1[tid] += sh1[tid + o]; }
        __syncthreads();
    }
    if (tid == 0) {
        const float invN = 1.0f / (float)NTOT;
        float mean = sh0[0] * invN;
        float var  = sh1[0] * invN - mean * mean;
        float scale = gamma[0] * rsqrtf(var + EPSV);
        g_stats[0] = scale;
        g_stats[1] = beta[0] - mean * scale;
    }
}

// ---------------------------------------------------------------------------
// Kernel 3: W -> fp16 hi/lo
// ---------------------------------------------------------------------------
__global__ void split_w(const float* __restrict__ W) {
    int i = blockIdx.x * 256 + threadIdx.x;
    float w = W[i];
    __half h = __float2half_rn(w);
    g_w_h[i] = h;
    g_w_l[i] = __float2half_rn(w - __half2float(h));
}

// ---------------------------------------------------------------------------
// Kernel 4: normalize + transpose: x[b,t,f] -> yT_h[b,f,t] (fp16)
// Tile 64(t) x 32(f); 16B fp16 stores (8 t-values per thread).
// ---------------------------------------------------------------------------
__global__ void convert_transpose(const float* __restrict__ x) {
    __shared__ float tile[64][33];
    const int b = blockIdx.z, t0 = blockIdx.x * 64, f0 = blockIdx.y * 32;
    const int tx = threadIdx.x, ty = threadIdx.y;   // 32 x 8
    const float scale = g_stats[0], shift = g_stats[1];
    const float* __restrict__ xb = x + ((size_t)b * TDIM + t0) * FDIM + f0;
#pragma unroll
    for (int j = 0; j < 8; j++)
        tile[ty + j * 8][tx] = xb[(size_t)(ty + j * 8) * FDIM + tx];
    __syncthreads();

    const int tid = ty * 32 + tx;
    const int fl = tid >> 3;          // 0..31
    const int tc = (tid & 7) * 8;     // 0..56
    __half hv[8];
#pragma unroll
    for (int q = 0; q < 8; q++) {
        float y = fmaf(tile[tc + q][fl], scale, shift);
        hv[q] = __float2half_rn(y);
    }
    __half* __restrict__ ph = g_yT_h + ((size_t)b * FDIM + f0 + fl) * TDIM + t0 + tc;
    *(uint4*)ph = *(const uint4*)hv;
}

// ---------------------------------------------------------------------------
// Kernel 5: fp16 mma.sync GEMM + fused epilogue
// CTA 128(f) x 128(u), BK=16, 4-stage cp.async pipeline, 1 sync/iter.
// 8 warps (2m x 4n), warp tile 64x32 m16n8k16. D = Ah*Wh + Ah*Wl.
// ---------------------------------------------------------------------------
#define GM 128
#define GN 128
#define KITER 32            // 512 / 16
#define ROWB 48             // 16 fp16 (32B) + 16B pad -> conflict-free ldmatrix

#define PL_SZ    (128 * ROWB)          // 6144
#define STAGE_SZ (3 * PL_SZ)           // 18432: Ah | Wh | Wl
#define SMEM_SZ  (4 * STAGE_SZ)        // 73728 (epilogue reuse needs 67584)

__global__ __launch_bounds__(256, 2)
void gemm_tc(const float* __restrict__ x, const float* __restrict__ bias,
             float* __restrict__ out) {
    extern __shared__ char smem[];
    const uint32_t sb = smem_u32(smem);
    const int tid = threadIdx.x, wid = tid >> 5, lid = tid & 31;
    const int wm = wid >> 2, wn = wid & 3;           // 2 x 4 warp grid
    const int b = blockIdx.z, f0 = blockIdx.x * GM, u0 = blockIdx.y * GN;

    const __half* __restrict__ Ah = g_yT_h + ((size_t)b * FDIM + f0) * TDIM;
    const __half* __restrict__ Bh = g_w_h + (size_t)u0 * TDIM;
    const __half* __restrict__ Bl = g_w_l + (size_t)u0 * TDIM;

    // loader: 128 rows x 2 chunks(16B) per plane; tid covers all 256 slots
    const int lrow = tid >> 1, lc = tid & 1;
    const uint32_t lso = (uint32_t)(lrow * ROWB + lc * 16);
    const size_t lgo_base = (size_t)lrow * TDIM + lc * 8;

    // ldmatrix lane offsets
    const uint32_t a_off = (uint32_t)((wm * 64 + (lid & 15)) * ROWB + (lid >> 4) * 16);
    const uint32_t b_off = (uint32_t)((wn * 32 + (lid & 7) + ((lid >> 4) * 8)) * ROWB
                                      + ((lid >> 3) & 1) * 16);

    float acc[4][4][4];
#pragma unroll
    for (int i = 0; i < 4; i++)
#pragma unroll
        for (int j = 0; j < 4; j++)
#pragma unroll
            for (int q = 0; q < 4; q++) acc[i][j][q] = 0.f;

    // ---- prologue: stages 0..2
#pragma unroll
    for (int s = 0; s < 3; s++) {
        const uint32_t st = sb + s * STAGE_SZ;
        const size_t g = lgo_base + s * 16;
        cp16(st + lso,             Ah + g);
        cp16(st + PL_SZ + lso,     Bh + g);
        cp16(st + 2 * PL_SZ + lso, Bl + g);
        asm volatile("cp.async.commit_group;" ::: "memory");
    }

    for (int kc = 0; kc < KITER; kc++) {
        if (kc < KITER - 2)
            asm volatile("cp.async.wait_group 2;" ::: "memory");
        else if (kc == KITER - 2)
            asm volatile("cp.async.wait_group 1;" ::: "memory");
        else
            asm volatile("cp.async.wait_group 0;" ::: "memory");
        __syncthreads();

        // refill stage kc+3 (its buffer was consumed at iter kc-1; barrier above
        // guarantees all warps are past that read)
        if (kc + 3 < KITER) {
            const uint32_t st = sb + ((kc + 3) & 3) * STAGE_SZ;
            const size_t g = lgo_base + (size_t)(kc + 3) * 16;
            cp16(st + lso,             Ah + g);
            cp16(st + PL_SZ + lso,     Bh + g);
            cp16(st + 2 * PL_SZ + lso, Bl + g);
            asm volatile("cp.async.commit_group;" ::: "memory");
        }

        const uint32_t st = sb + (kc & 3) * STAGE_SZ;
        uint32_t ah[4][4], bh[2][4], bl[2][4];
#pragma unroll
        for (int mt = 0; mt < 4; mt++)
            ldsm4(ah[mt], st + a_off + mt * (16 * ROWB));
#pragma unroll
        for (int nt = 0; nt < 2; nt++)
            ldsm4(bh[nt], st + PL_SZ + b_off + nt * (16 * ROWB));
#pragma unroll
        for (int nt = 0; nt < 2; nt++)
            ldsm4(bl[nt], st + 2 * PL_SZ + b_off + nt * (16 * ROWB));
#pragma unroll
        for (int mt = 0; mt < 4; mt++)
#pragma unroll
            for (int nf = 0; nf < 4; nf++)
                mma16816(acc[mt][nf], ah[mt], &bh[nf >> 1][(nf & 1) * 2]);
#pragma unroll
        for (int mt = 0; mt < 4; mt++)
#pragma unroll
            for (int nf = 0; nf < 4; nf++)
                mma16816(acc[mt][nf], ah[mt], &bl[nf >> 1][(nf & 1) * 2]);
    }
    __syncthreads();

    // ---- epilogue: transpose through smem, then coalesced f-major stores
    float* __restrict__ S = (float*)smem;     // [u_local][f_local], stride 132
    const int qrow = lid >> 2, qcol = (lid & 3) * 2;
#pragma unroll
    for (int mt = 0; mt < 4; mt++)
#pragma unroll
        for (int nf = 0; nf < 4; nf++) {
            const int fl = wm * 64 + mt * 16 + qrow;
            const int ul = wn * 32 + nf * 8 + qcol;
            S[(ul)     * 132 + fl]     = acc[mt][nf][0];
            S[(ul + 1) * 132 + fl]     = acc[mt][nf][1];
            S[(ul)     * 132 + fl + 8] = acc[mt][nf][2];
            S[(ul + 1) * 132 + fl + 8] = acc[mt][nf][3];
        }
    __syncthreads();

    const int fl4 = (tid & 31) * 4, ur = tid >> 5;
#pragma unroll
    for (int up = 0; up < 16; up++) {
        const int ul = up * 8 + ur;
        const int u = u0 + ul;
        const float bv = __ldg(&bias[u]);
        const size_t gidx = ((size_t)b * TDIM + u) * FDIM + f0 + fl4;
        float4 xv = *(const float4*)(x + gidx);
        const float* sp = S + ul * 132 + fl4;
        float4 o;
        o.x = xv.x + fmaxf(sp[0] + bv, 0.f);
        o.y = xv.y + fmaxf(sp[1] + bv, 0.f);
        o.z = xv.z + fmaxf(sp[2] + bv, 0.f);
        o.w = xv.w + fmaxf(sp[3] + bv, 0.f);
        *(float4*)(out + gidx) = o;
    }
}

// ---------------------------------------------------------------------------
extern "C" void kernel_launch(void* const* d_in, const int* in_sizes, int n_in,
                              void* d_out, int out_size) {
    const float* x     = (const float*)d_in[0];
    const float* W     = (const float*)d_in[1];
    const float* bias  = (const float*)d_in[2];
    const float* gamma = (const float*)d_in[3];
    const float* beta  = (const float*)d_in[4];
    float* out = (float*)d_out;

    static bool attr_set = false;
    if (!attr_set) {
        cudaFuncSetAttribute(gemm_tc, cudaFuncAttributeMaxDynamicSharedMemorySize, SMEM_SZ);
        attr_set = true;
    }

    reduce_partials<<<RED_BLOCKS, RED_THREADS>>>(x);
    finalize_stats<<<1, 1024>>>(gamma, beta);
    split_w<<<(TDIM * TDIM) / 256, 256>>>(W);
    convert_transpose<<<dim3(TDIM / 64, FDIM / 32, BSZ), dim3(32, 8)>>>(x);

    dim3 grid(FDIM / GM, TDIM / GN, BSZ);
    gemm_tc<<<grid, 256, SMEM_SZ>>>(x, bias, out);
}

// round 5
// speedup vs baseline: 2.9650x; 1.0943x over previous
#include <cuda_runtime.h>
#include <cuda_fp16.h>
#include <cstdint>
#include <cstddef>

// Problem: B=64, T=512, F=1024
//   stats over all x; y = x*scale + shift
//   out[b,t,f] = x[b,t,f] + relu( sum_t' y[b,t',f]*W[t,t'] + bias[t] )
// Refactor: h[u,f] = scale * (sum_t' x[t',f]*W[u,t']) + shift*wsum[u]
// GEMM on raw fp16 x-transpose vs fp16 W; normalization folded into epilogue.

#define BSZ  64
#define TDIM 512
#define FDIM 1024
#define NTOT (BSZ * TDIM * FDIM)
#define EPSV 1e-5f

#define CT_BLOCKS (8 * 32 * BSZ)   // convert grid: (T/64, F/32, B) = 16384

__device__ float g_partial[2 * CT_BLOCKS];
__device__ float g_stats[2];                 // {scale, shift}
__device__ float g_wsum[TDIM];               // fp32 row sums of W

__device__ __align__(16) __half g_xT[(size_t)BSZ * FDIM * TDIM];  // [b][f][t]
__device__ __align__(16) __half g_w_h[TDIM * TDIM];               // [u][t]

// ---------------------------------------------------------------------------
__device__ __forceinline__ uint32_t smem_u32(const void* p) {
    uint32_t a;
    asm("{ .reg .u64 t; cvta.to.shared.u64 t, %1; cvt.u32.u64 %0, t; }"
        : "=r"(a) : "l"(p));
    return a;
}
__device__ __forceinline__ void cp16(uint32_t s, const void* g) {
    asm volatile("cp.async.cg.shared.global [%0], [%1], 16;" :: "r"(s), "l"(g) : "memory");
}
__device__ __forceinline__ void ldsm4(uint32_t* r, uint32_t addr) {
    asm volatile("ldmatrix.sync.aligned.m8n8.x4.shared.b16 {%0,%1,%2,%3}, [%4];"
                 : "=r"(r[0]), "=r"(r[1]), "=r"(r[2]), "=r"(r[3]) : "r"(addr));
}
__device__ __forceinline__ void mma16816(float* c, const uint32_t* a, const uint32_t* b) {
    asm volatile("mma.sync.aligned.m16n8k16.row.col.f32.f16.f16.f32 "
                 "{%0,%1,%2,%3}, {%4,%5,%6,%7}, {%8,%9}, {%0,%1,%2,%3};"
                 : "+f"(c[0]), "+f"(c[1]), "+f"(c[2]), "+f"(c[3])
                 : "r"(a[0]), "r"(a[1]), "r"(a[2]), "r"(a[3]), "r"(b[0]), "r"(b[1]));
}

// ---------------------------------------------------------------------------
// Kernel 1: fused transpose-to-fp16 + stats partials (x read ONCE)
// Tile 64(t) x 32(f), 256 threads.
// ---------------------------------------------------------------------------
__global__ void convert_reduce(const float* __restrict__ x) {
    __shared__ float tile[64][33];
    __shared__ float sr0[256], sr1[256];
    const int b = blockIdx.z, t0 = blockIdx.x * 64, f0 = blockIdx.y * 32;
    const int tx = threadIdx.x, ty = threadIdx.y;   // 32 x 8
    const int tid = ty * 32 + tx;
    const float* __restrict__ xb = x + ((size_t)b * TDIM + t0) * FDIM + f0;

    float s = 0.f, ss = 0.f;
#pragma unroll
    for (int j = 0; j < 8; j++) {
        float v = xb[(size_t)(ty + j * 8) * FDIM + tx];
        tile[ty + j * 8][tx] = v;
        s += v; ss += v * v;
    }
    sr0[tid] = s; sr1[tid] = ss;
    __syncthreads();

    // transpose-store fp16 (raw x, no normalization)
    const int fl = tid >> 3;          // 0..31
    const int tc = (tid & 7) * 8;     // 0..56
    __half hv[8];
#pragma unroll
    for (int q = 0; q < 8; q++) hv[q] = __float2half_rn(tile[tc + q][fl]);
    __half* __restrict__ ph = g_xT + ((size_t)b * FDIM + f0 + fl) * TDIM + t0 + tc;
    *(uint4*)ph = *(const uint4*)hv;

    // block reduce partials
#pragma unroll
    for (int o = 128; o > 0; o >>= 1) {
        if (tid < o) { sr0[tid] += sr0[tid + o]; sr1[tid] += sr1[tid + o]; }
        __syncthreads();
    }
    if (tid == 0) {
        const int blin = blockIdx.x + 8 * (blockIdx.y + 32 * blockIdx.z);
        g_partial[blin]             = sr0[0];
        g_partial[CT_BLOCKS + blin] = sr1[0];
    }
}

// ---------------------------------------------------------------------------
// Kernel 2: finalize stats (16384 partials each)
// ---------------------------------------------------------------------------
__global__ void finalize_stats(const float* __restrict__ gamma,
                               const float* __restrict__ beta) {
    const int tid = threadIdx.x;   // 1024
    float s = 0.f, ss = 0.f;
#pragma unroll
    for (int q = 0; q < CT_BLOCKS / 1024; q++) {
        s  += g_partial[q * 1024 + tid];
        ss += g_partial[CT_BLOCKS + q * 1024 + tid];
    }
    __shared__ float sh0[1024], sh1[1024];
    sh0[tid] = s; sh1[tid] = ss;
    __syncthreads();
#pragma unroll
    for (int o = 512; o > 0; o >>= 1) {
        if (tid < o) { sh0[tid] += sh0[tid + o]; sh1[tid] += sh1[tid + o]; }
        __syncthreads();
    }
    if (tid == 0) {
        const float invN = 1.0f / (float)NTOT;
        float mean = sh0[0] * invN;
        float var  = sh1[0] * invN - mean * mean;
        float scale = gamma[0] * rsqrtf(var + EPSV);
        g_stats[0] = scale;
        g_stats[1] = beta[0] - mean * scale;
    }
}

// ---------------------------------------------------------------------------
// Kernel 3: W -> fp16 + fp32 row sums. One block per row u.
// ---------------------------------------------------------------------------
__global__ void prep_w(const float* __restrict__ W) {
    const int u = blockIdx.x, tid = threadIdx.x;   // 256 threads
    __shared__ float sr[256];
    float s = 0.f;
#pragma unroll
    for (int q = 0; q < 2; q++) {
        const int t = q * 256 + tid;
        float w = W[(size_t)u * TDIM + t];
        g_w_h[(size_t)u * TDIM + t] = __float2half_rn(w);
        s += w;
    }
    sr[tid] = s;
    __syncthreads();
#pragma unroll
    for (int o = 128; o > 0; o >>= 1) {
        if (tid < o) sr[tid] += sr[tid + o];
        __syncthreads();
    }
    if (tid == 0) g_wsum[u] = sr[0];
}

// ---------------------------------------------------------------------------
// Kernel 4: fp16 mma.sync GEMM + fused normalize/bias/relu/residual epilogue
// CTA 128(f) x 128(u), BK=16, 4-stage cp.async, 8 warps (2m x 4n), 64x32 warp.
// ---------------------------------------------------------------------------
#define GM 128
#define GN 128
#define KITER 32            // 512 / 16
#define ROWB 48             // 16 fp16 (32B) + 16B pad

#define PL_SZ    (128 * ROWB)          // 6144
#define STAGE_SZ (2 * PL_SZ)           // 12288: A | W
#define SMEM_SZ  67584                 // max(4*STAGE_SZ=49152, epilogue 128*132*4)

__global__ __launch_bounds__(256, 2)
void gemm_tc(const float* __restrict__ x, const float* __restrict__ bias,
             float* __restrict__ out) {
    extern __shared__ char smem[];
    const uint32_t sb = smem_u32(smem);
    const int tid = threadIdx.x, wid = tid >> 5, lid = tid & 31;
    const int wm = wid >> 2, wn = wid & 3;
    const int b = blockIdx.z, f0 = blockIdx.x * GM, u0 = blockIdx.y * GN;

    const __half* __restrict__ Ap = g_xT + ((size_t)b * FDIM + f0) * TDIM;
    const __half* __restrict__ Bp = g_w_h + (size_t)u0 * TDIM;

    // loader: per plane 128 rows x 2 chunks(16B); 256 threads -> 1 chunk each
    const int lrow = tid >> 1, lc = tid & 1;
    const uint32_t lso = (uint32_t)(lrow * ROWB + lc * 16);
    const size_t lgo_base = (size_t)lrow * TDIM + lc * 8;

    const uint32_t a_off = (uint32_t)((wm * 64 + (lid & 15)) * ROWB + (lid >> 4) * 16);
    const uint32_t b_off = (uint32_t)((wn * 32 + (lid & 7) + ((lid >> 4) * 8)) * ROWB
                                      + ((lid >> 3) & 1) * 16);

    float acc[4][4][4];
#pragma unroll
    for (int i = 0; i < 4; i++)
#pragma unroll
        for (int j = 0; j < 4; j++)
#pragma unroll
            for (int q = 0; q < 4; q++) acc[i][j][q] = 0.f;

#pragma unroll
    for (int s = 0; s < 3; s++) {
        const uint32_t st = sb + s * STAGE_SZ;
        const size_t g = lgo_base + s * 16;
        cp16(st + lso,         Ap + g);
        cp16(st + PL_SZ + lso, Bp + g);
        asm volatile("cp.async.commit_group;" ::: "memory");
    }

    for (int kc = 0; kc < KITER; kc++) {
        if (kc < KITER - 2)
            asm volatile("cp.async.wait_group 2;" ::: "memory");
        else if (kc == KITER - 2)
            asm volatile("cp.async.wait_group 1;" ::: "memory");
        else
            asm volatile("cp.async.wait_group 0;" ::: "memory");
        __syncthreads();

        if (kc + 3 < KITER) {
            const uint32_t st = sb + ((kc + 3) & 3) * STAGE_SZ;
            const size_t g = lgo_base + (size_t)(kc + 3) * 16;
            cp16(st + lso,         Ap + g);
            cp16(st + PL_SZ + lso, Bp + g);
            asm volatile("cp.async.commit_group;" ::: "memory");
        }

        const uint32_t st = sb + (kc & 3) * STAGE_SZ;
        uint32_t ah[4][4], bh[2][4];
#pragma unroll
        for (int mt = 0; mt < 4; mt++)
            ldsm4(ah[mt], st + a_off + mt * (16 * ROWB));
#pragma unroll
        for (int nt = 0; nt < 2; nt++)
            ldsm4(bh[nt], st + PL_SZ + b_off + nt * (16 * ROWB));
#pragma unroll
        for (int mt = 0; mt < 4; mt++)
#pragma unroll
            for (int nf = 0; nf < 4; nf++)
                mma16816(acc[mt][nf], ah[mt], &bh[nf >> 1][(nf & 1) * 2]);
    }
    __syncthreads();

    // epilogue: transpose via smem, then h = scale*acc + shift*wsum[u] + bias[u]
    const float scale = g_stats[0], shift = g_stats[1];
    float* __restrict__ S = (float*)smem;     // [u_local][f_local], stride 132
    const int qrow = lid >> 2, qcol = (lid & 3) * 2;
#pragma unroll
    for (int mt = 0; mt < 4; mt++)
#pragma unroll
        for (int nf = 0; nf < 4; nf++) {
            const int fl = wm * 64 + mt * 16 + qrow;
            const int ul = wn * 32 + nf * 8 + qcol;
            S[(ul)     * 132 + fl]     = acc[mt][nf][0];
            S[(ul + 1) * 132 + fl]     = acc[mt][nf][1];
            S[(ul)     * 132 + fl + 8] = acc[mt][nf][2];
            S[(ul + 1) * 132 + fl + 8] = acc[mt][nf][3];
        }
    __syncthreads();

    const int fl4 = (tid & 31) * 4, ur = tid >> 5;
#pragma unroll
    for (int up = 0; up < 16; up++) {
        const int ul = up * 8 + ur;
        const int u = u0 + ul;
        const float cu = shift * g_wsum[u] + __ldg(&bias[u]);
        const size_t gidx = ((size_t)b * TDIM + u) * FDIM + f0 + fl4;
        float4 xv = *(const float4*)(x + gidx);
        const float* sp = S + ul * 132 + fl4;
        float4 o;
        o.x = xv.x + fmaxf(fmaf(scale, sp[0], cu), 0.f);
        o.y = xv.y + fmaxf(fmaf(scale, sp[1], cu), 0.f);
        o.z = xv.z + fmaxf(fmaf(scale, sp[2], cu), 0.f);
        o.w = xv.w + fmaxf(fmaf(scale, sp[3], cu), 0.f);
        *(float4*)(out + gidx) = o;
    }
}

// ---------------------------------------------------------------------------
extern "C" void kernel_launch(void* const* d_in, const int* in_sizes, int n_in,
                              void* d_out, int out_size) {
    const float* x     = (const float*)d_in[0];
    const float* W     = (const float*)d_in[1];
    const float* bias  = (const float*)d_in[2];
    const float* gamma = (const float*)d_in[3];
    const float* beta  = (const float*)d_in[4];
    float* out = (float*)d_out;

    static bool attr_set = false;
    if (!attr_set) {
        cudaFuncSetAttribute(gemm_tc, cudaFuncAttributeMaxDynamicSharedMemorySize, SMEM_SZ);
        attr_set = true;
    }

    convert_reduce<<<dim3(TDIM / 64, FDIM / 32, BSZ), dim3(32, 8)>>>(x);
    finalize_stats<<<1, 1024>>>(gamma, beta);
    prep_w<<<TDIM, 256>>>(W);

    dim3 grid(FDIM / GM, TDIM / GN, BSZ);
    gemm_tc<<<grid, 256, SMEM_SZ>>>(x, bias, out);
}